// round 12
// baseline (speedup 1.0000x reference)
#include <cuda_runtime.h>
#include <cuda_bf16.h>
#include <cstdint>

// BoxCrop: crop -> aspect-preserving bilinear resize (long side = 336) -> pad(127)
// images: [64, 3, 768, 768] f32, boxes: [64, 4] i32 (XYWH), out: [64, 3, 336, 336] f32
// Per-IMAGE params precomputed (64-thread kernel); hot kernel = 2 px/thread,
// batched 24 gathers, float2 stores, zero divides, minimal prologue.

#define O_SIZE   336
#define IMG_H    768
#define IMG_W    768
#define IMG_HW   (IMG_H * IMG_W)
#define FILL_V   127.0f
#define GROUPS_X 168         // 336 / 2
#define BATCH    64

__device__ int4   g_ip [BATCH];   // {pad_left, pad_top, new_w, new_h}
__device__ int4   g_ip2[BATCH];   // {xlo, xhi, ylo, yhi}
__device__ float4 g_fp [BATCH];   // {step_x, step_y, xb-0.5, yb-0.5}

__global__ void __launch_bounds__(BATCH) precompute_kernel(const int* __restrict__ boxes)
{
    const int b = threadIdx.x;
    const int4 box = __ldg((const int4*)boxes + b);
    const int xb = box.x, yb = box.y, wb = box.z, hb = box.w;
    const float wf = (float)wb;
    const float hf = (float)hb;

    // Exact fp32 matching JAX: scale = 336/max; round-half-even via rintf
    const float scale = 336.0f / fmaxf(wf, hf);
    const int new_w = (int)rintf(wf * scale);
    const int new_h = (int)rintf(hf * scale);
    const int pad_top  = (hb <  wb) ? (O_SIZE - new_h) / 2 : 0;
    const int pad_left = (hb >= wb) ? (O_SIZE - new_w) / 2 : 0;

    g_ip [b] = make_int4(pad_left, pad_top, new_w, new_h);
    g_ip2[b] = make_int4(xb, xb + wb - 1, yb, yb + hb - 1);
    g_fp [b] = make_float4(wf / (float)new_w, hf / (float)new_h,
                           (float)xb - 0.5f, (float)yb - 0.5f);
}

__global__ void __launch_bounds__(256) boxcrop_kernel(
    const float* __restrict__ images,
    float* __restrict__ out)
{
    const int b  = blockIdx.z;
    const int g  = blockIdx.x * blockDim.x + threadIdx.x;   // x-group index
    const int oy = blockIdx.y * blockDim.y + threadIdx.y;
    if (g >= GROUPS_X || oy >= O_SIZE) return;
    const int ox0 = g * 2;

    // warp-uniform broadcast loads, L1/L2 resident
    const int4   ip  = __ldg(&g_ip [b]);
    const int4   ip2 = __ldg(&g_ip2[b]);
    const float4 fp  = __ldg(&g_fp [b]);

    float2* outp = (float2*)(out + ((size_t)b * 3) * (O_SIZE * O_SIZE) + oy * O_SIZE + ox0);
    const int cstride2 = (O_SIZE * O_SIZE) / 2;

    const int iy  = oy  - ip.y;
    const int ix0 = ox0 - ip.x;
    const int new_w = ip.z;

    const float2 fill2 = make_float2(FILL_V, FILL_V);

    if ((unsigned)iy >= (unsigned)ip.w || ix0 + 1 < 0 || ix0 >= new_w) {
        outp[0]            = fill2;
        outp[cstride2]     = fill2;
        outp[2 * cstride2] = fill2;
        return;
    }

    // ---- y side ----
    const float src_y = fp.w + ((float)iy + 0.5f) * fp.y;
    const float y0f = floorf(src_y);
    const float wy  = src_y - y0f;
    const int y0i = (int)y0f;
    const int y0 = min(max(y0i,     ip2.z), ip2.w);   // clamp from UNCLAMPED idx
    const int y1 = min(max(y0i + 1, ip2.z), ip2.w);
    const int r0 = y0 * IMG_W;
    const int r1 = y1 * IMG_W;
    const float owy = 1.0f - wy;

    // ---- x side (per pixel; clamp from UNCLAMPED floor index) ----
    int   xi0[2], xi1[2];
    float w00[2], w01[2], w10[2], w11[2];
    #pragma unroll
    for (int j = 0; j < 2; j++) {
        const float src_x = fp.z + ((float)(ix0 + j) + 0.5f) * fp.x;
        const float x0f = floorf(src_x);
        const float wx  = src_x - x0f;
        const float owx = 1.0f - wx;
        w00[j] = owx * owy;  w01[j] = wx * owy;
        w10[j] = owx * wy;   w11[j] = wx * wy;
        const int x0i = (int)x0f;
        xi0[j] = min(max(x0i,     ip2.x), ip2.y);
        xi1[j] = min(max(x0i + 1, ip2.x), ip2.y);
    }

    const float* img = images + (size_t)b * 3 * IMG_HW;

    // ---- batch all 24 gather loads (3 channels x 2 px x 4 taps) for MLP ----
    float v00[3][2], v01[3][2], v10[3][2], v11[3][2];
    #pragma unroll
    for (int c = 0; c < 3; c++) {
        const float* p = img + c * IMG_HW;
        #pragma unroll
        for (int j = 0; j < 2; j++) {
            v00[c][j] = __ldg(p + r0 + xi0[j]);
            v01[c][j] = __ldg(p + r0 + xi1[j]);
            v10[c][j] = __ldg(p + r1 + xi0[j]);
            v11[c][j] = __ldg(p + r1 + xi1[j]);
        }
    }

    const bool va = ((unsigned)ix0       < (unsigned)new_w);
    const bool vb = ((unsigned)(ix0 + 1) < (unsigned)new_w);

    // ---- blend (1 MUL + 3 FMA per channel-pixel) + store ----
    #pragma unroll
    for (int c = 0; c < 3; c++) {
        float r[2];
        #pragma unroll
        for (int j = 0; j < 2; j++) {
            float v = v00[c][j] * w00[j];
            v = fmaf(v01[c][j], w01[j], v);
            v = fmaf(v10[c][j], w10[j], v);
            v = fmaf(v11[c][j], w11[j], v);
            r[j] = v;
        }
        float2 o;
        o.x = va ? r[0] : FILL_V;
        o.y = vb ? r[1] : FILL_V;
        outp[c * cstride2] = o;
    }
}

extern "C" void kernel_launch(void* const* d_in, const int* in_sizes, int n_in,
                              void* d_out, int out_size)
{
    const float* images = (const float*)d_in[0];
    const int*   boxes  = (const int*)d_in[1];
    float*       out    = (float*)d_out;

    precompute_kernel<<<1, BATCH>>>(boxes);

    dim3 block(32, 8, 1);
    dim3 grid((GROUPS_X + 31) / 32, (O_SIZE + 7) / 8, BATCH);
    boxcrop_kernel<<<grid, block>>>(images, out);
}